// round 6
// baseline (speedup 1.0000x reference)
#include <cuda_runtime.h>
#include <cuda_bf16.h>

#define N_NODES 50000
#define N_EDGES 800000
#define D 64

// Scratch (device globals: allocation-free per harness rules)
__device__ float g_xw[N_NODES * D];      // xs = (x@W) * dis[row]
__device__ float g_dis[N_NODES];
__device__ int   g_degi[N_NODES];        // edge-only in-degree
__device__ int   g_off[N_NODES];         // CSR offsets (exclusive scan of degi)
__device__ int   g_cur[N_NODES];         // fill cursors
__device__ int   g_srcs[N_EDGES];        // CSR src lists grouped by dst

// ---------------------------------------------------------------------------
// K0: zero counters (must run every call — graph replays)
__global__ void k_zero() {
    int i = blockIdx.x * blockDim.x + threadIdx.x;
    if (i < N_NODES) { g_degi[i] = 0; g_cur[i] = 0; }
}

// K1: count in-degrees (dst row of edge_index, int32!)
__global__ void k_count(const int* __restrict__ ei) {
    int e = blockIdx.x * blockDim.x + threadIdx.x;
    if (e < N_EDGES) {
        int d = ei[N_EDGES + e];
        atomicAdd(&g_degi[d], 1);
    }
}

// K2: single-block exclusive scan of g_degi -> g_off, and dis = rsqrt(deg+1)
__global__ void __launch_bounds__(1024) k_scan() {
    __shared__ int sp[1024];
    const int t = threadIdx.x;
    const int CH = (N_NODES + 1023) / 1024;   // 49
    const int base = t * CH;

    int sum = 0;
    for (int k = 0; k < CH; k++) {
        int i = base + k;
        if (i < N_NODES) sum += g_degi[i];
    }
    sp[t] = sum;
    __syncthreads();

    // Hillis-Steele inclusive scan over 1024 partials
    for (int ofs = 1; ofs < 1024; ofs <<= 1) {
        int v = 0;
        if (t >= ofs) v = sp[t - ofs];
        __syncthreads();
        sp[t] += v;
        __syncthreads();
    }

    int off = (t == 0) ? 0 : sp[t - 1];
    for (int k = 0; k < CH; k++) {
        int i = base + k;
        if (i < N_NODES) {
            g_off[i] = off;
            int dg = g_degi[i];
            off += dg;
            g_dis[i] = rsqrtf((float)(dg + 1));   // +1 self loop
        }
    }
}

// K3: xs = (x @ W) * dis[row]   (W in smem, one row per thread)
__global__ void __launch_bounds__(256) k_gemm(const float* __restrict__ x,
                                              const float* __restrict__ W) {
    __shared__ float sW[D * D];
    int tid = threadIdx.x;
    #pragma unroll
    for (int i = tid; i < D * D; i += 256) sW[i] = W[i];
    __syncthreads();

    int r = blockIdx.x * 256 + tid;
    if (r >= N_NODES) return;

    float acc[D];
    #pragma unroll
    for (int c = 0; c < D; c++) acc[c] = 0.0f;

    const float4* xr = reinterpret_cast<const float4*>(x + (size_t)r * D);
    #pragma unroll
    for (int kk = 0; kk < D / 4; kk++) {
        float4 xv = xr[kk];
        int k = kk * 4;
        #pragma unroll
        for (int c = 0; c < D; c++) {
            acc[c] += xv.x * sW[(k + 0) * D + c]
                    + xv.y * sW[(k + 1) * D + c]
                    + xv.z * sW[(k + 2) * D + c]
                    + xv.w * sW[(k + 3) * D + c];
        }
    }

    float dis = g_dis[r];
    float4* o = reinterpret_cast<float4*>(g_xw + (size_t)r * D);
    #pragma unroll
    for (int c = 0; c < D / 4; c++)
        o[c] = make_float4(acc[4 * c + 0] * dis, acc[4 * c + 1] * dis,
                           acc[4 * c + 2] * dis, acc[4 * c + 3] * dis);
}

// K4: bucket-fill CSR src lists (int32 edge index)
__global__ void k_fill(const int* __restrict__ ei) {
    int e = blockIdx.x * blockDim.x + threadIdx.x;
    if (e < N_EDGES) {
        int s = ei[e];
        int d = ei[N_EDGES + e];
        int pos = g_off[d] + atomicAdd(&g_cur[d], 1);
        g_srcs[pos] = s;
    }
}

// K5: gather. One warp per node; each lane owns 2 feature columns (float2).
// out[i] = dis[i] * (xs[i] + sum_j xs[src_j]) + b
__global__ void __launch_bounds__(256) k_gather(const float* __restrict__ b,
                                                float* __restrict__ out) {
    int warp = (blockIdx.x * 256 + threadIdx.x) >> 5;
    int lane = threadIdx.x & 31;
    if (warp >= N_NODES) return;
    const int i = warp;

    const float2* xs2 = reinterpret_cast<const float2*>(g_xw);
    const int col2 = i * (D / 2) + lane;

    float2 acc = __ldg(&xs2[col2]);                 // self term xs[i]
    const int off = g_off[i];
    const int deg = g_degi[i];

    int j = 0;
    for (; j + 4 <= deg; j += 4) {                  // MLP = 4
        int s0 = __ldg(&g_srcs[off + j + 0]);
        int s1 = __ldg(&g_srcs[off + j + 1]);
        int s2 = __ldg(&g_srcs[off + j + 2]);
        int s3 = __ldg(&g_srcs[off + j + 3]);
        float2 v0 = __ldg(&xs2[s0 * (D / 2) + lane]);
        float2 v1 = __ldg(&xs2[s1 * (D / 2) + lane]);
        float2 v2 = __ldg(&xs2[s2 * (D / 2) + lane]);
        float2 v3 = __ldg(&xs2[s3 * (D / 2) + lane]);
        acc.x += v0.x + v1.x + v2.x + v3.x;
        acc.y += v0.y + v1.y + v2.y + v3.y;
    }
    for (; j < deg; j++) {
        int s = __ldg(&g_srcs[off + j]);
        float2 v = __ldg(&xs2[s * (D / 2) + lane]);
        acc.x += v.x;
        acc.y += v.y;
    }

    float dis = g_dis[i];
    float2 bb = __ldg(reinterpret_cast<const float2*>(b) + lane);
    float2 o;
    o.x = acc.x * dis + bb.x;
    o.y = acc.y * dis + bb.y;
    reinterpret_cast<float2*>(out)[col2] = o;
}

extern "C" void kernel_launch(void* const* d_in, const int* in_sizes, int n_in,
                              void* d_out, int out_size) {
    const float* x  = (const float*)d_in[0];
    const int*   ei = (const int*)d_in[1];     // int64 in reference, delivered as int32
    const float* W  = (const float*)d_in[2];
    const float* b  = (const float*)d_in[3];
    float* out = (float*)d_out;

    (void)in_sizes; (void)n_in; (void)out_size;

    k_zero  <<<(N_NODES + 255) / 256, 256>>>();
    k_count <<<(N_EDGES + 255) / 256, 256>>>(ei);
    k_scan  <<<1, 1024>>>();
    k_gemm  <<<(N_NODES + 255) / 256, 256>>>(x, W);
    k_fill  <<<(N_EDGES + 255) / 256, 256>>>(ei);
    k_gather<<<(N_NODES * 32 + 255) / 256, 256>>>(b, out);
}